// round 2
// baseline (speedup 1.0000x reference)
#include <cuda_runtime.h>
#include <cstdint>

// ============================================================================
// Fused attention: O = dropout(softmax(Q K^T * sqrt(128))) V
//   B=4, Q=V=4096, H=128, fp32.
//   Dropout mask reproduces jax.random.bernoulli(jax.random.key(42), 0.9, (4,4096,4096))
//   with the PARTITIONABLE threefry path (JAX default since 2024):
//     per element m:  (o1,o2) = threefry2x32(key=(0,42), ctr=(0, m));  bits = o1 ^ o2
//     keep  <=>  bits < 7549747*512   ( (bits>>9)/2^23 < 0.9f )
// ============================================================================

namespace {
constexpr int BQ      = 64;    // q rows per CTA
constexpr int BK      = 64;    // key rows per block iteration
constexpr int H       = 128;
constexpr int SEQ     = 4096;
constexpr int THREADS = 256;
constexpr int KSTR    = 132;   // K smem row stride (pad for conflict-free column access)
constexpr int PSTR    = 68;    // P^T smem row stride (pad)
constexpr int SMEM_FLOATS = BQ * H + BK * KSTR + BK * PSTR;  // 20992 floats = 83968 B
constexpr uint32_t KEEP_THRESH = 3865470464u;  // bits < thresh  <=>  uniform < 0.9f
__device__ constexpr float QK_SCALE = 11.313708498984760390f;  // sqrt(128)
}

// threefry-2x32, 20 rounds, key = (0, 42)  (matches jax.random.key(42))
#define TF_ROUND(a, b, r) { (a) += (b); (b) = __funnelshift_l((b), (b), (r)); (b) ^= (a); }

__device__ __forceinline__ uint2 tf2x32_key0_42(uint32_t a, uint32_t b) {
    const uint32_t K1 = 42u;
    const uint32_t K2 = 0x1BD11BF0u;  // 0x1BD11BDA ^ 0 ^ 42
    // initial key injection (ks0 = 0 -> a unchanged)
    b += K1;
    TF_ROUND(a, b, 13) TF_ROUND(a, b, 15) TF_ROUND(a, b, 26) TF_ROUND(a, b, 6)
    a += K1; b += K2 + 1u;
    TF_ROUND(a, b, 17) TF_ROUND(a, b, 29) TF_ROUND(a, b, 16) TF_ROUND(a, b, 24)
    a += K2; b += 0u + 2u;
    TF_ROUND(a, b, 13) TF_ROUND(a, b, 15) TF_ROUND(a, b, 26) TF_ROUND(a, b, 6)
    a += 0u; b += K1 + 3u;
    TF_ROUND(a, b, 17) TF_ROUND(a, b, 29) TF_ROUND(a, b, 16) TF_ROUND(a, b, 24)
    a += K1; b += K2 + 4u;
    TF_ROUND(a, b, 13) TF_ROUND(a, b, 15) TF_ROUND(a, b, 26) TF_ROUND(a, b, 6)
    a += K2; b += 0u + 5u;
    return make_uint2(a, b);
}

__global__ __launch_bounds__(THREADS, 2)
void attn_dropout_kernel(const float* __restrict__ Qg_,
                         const float* __restrict__ Kg_,
                         const float* __restrict__ Vg_,
                         float* __restrict__ Og) {
    extern __shared__ float sm[];
    float* Qs = sm;                       // [BQ][H]      stride 128, read broadcast
    float* KV = sm + BQ * H;              // K: [BK][KSTR] / V: [BK][H]   (shared buffer)
    float* Ps = KV + BK * KSTR;           // P^T: [BK][PSTR]  Ps[j][i]

    const int tid  = threadIdx.x;
    const int g    = tid & 15;            // 16 column groups
    const int gq   = tid >> 4;            // 16 q-row groups
    const int qi   = gq << 2;             // first of 4 q rows owned
    const int qblk = blockIdx.x * BQ;
    const int b    = blockIdx.y;

    const float* Qg = Qg_ + (size_t)b * SEQ * H;
    const float* Kg = Kg_ + (size_t)b * SEQ * H;
    const float* Vg = Vg_ + (size_t)b * SEQ * H;

    // ---- load Q tile, pre-scaled by sqrt(128) ----
    #pragma unroll
    for (int i = 0; i < (BQ * H / 4) / THREADS; ++i) {   // 8 iters
        int idx = tid + i * THREADS;
        int row = idx >> 5, c4 = (idx & 31) << 2;
        float4 t = *(const float4*)(Qg + (size_t)(qblk + row) * H + c4);
        t.x *= QK_SCALE; t.y *= QK_SCALE; t.z *= QK_SCALE; t.w *= QK_SCALE;
        *(float4*)(Qs + row * H + c4) = t;
    }

    float m_run[4], l_run[4], acc[4][8];
    #pragma unroll
    for (int r = 0; r < 4; ++r) {
        m_run[r] = -1e30f; l_run[r] = 0.0f;
        #pragma unroll
        for (int c = 0; c < 8; ++c) acc[r][c] = 0.0f;
    }

    // flat mask index base: m = b*2^24 + q*2^12 + v  (q = qblk+qi+r, v = key index)
    const uint32_t mbase = ((uint32_t)b << 24) | ((uint32_t)(qblk + qi) << 12);

    for (int vb = 0; vb < SEQ; vb += BK) {
        __syncthreads();  // (a) previous PV / Q-load complete; KV + Ps free
        // ---- load K block (stride KSTR) ----
        #pragma unroll
        for (int i = 0; i < 8; ++i) {
            int idx = tid + i * THREADS;
            int row = idx >> 5, c4 = (idx & 31) << 2;
            *(float4*)(KV + row * KSTR + c4) =
                *(const float4*)(Kg + (size_t)(vb + row) * H + c4);
        }
        __syncthreads();  // (b)

        // ---- S = (scaled Q) K^T : 4x4 per thread, columns j = g + 16*jj ----
        float s[4][4];
        #pragma unroll
        for (int r = 0; r < 4; ++r)
            #pragma unroll
            for (int jj = 0; jj < 4; ++jj) s[r][jj] = 0.0f;

        #pragma unroll 2
        for (int h = 0; h < H; h += 4) {
            float4 q4[4];
            #pragma unroll
            for (int r = 0; r < 4; ++r)
                q4[r] = *(float4*)(Qs + (qi + r) * H + h);
            #pragma unroll
            for (int jj = 0; jj < 4; ++jj) {
                float4 k4 = *(float4*)(KV + (g + 16 * jj) * KSTR + h);
                #pragma unroll
                for (int r = 0; r < 4; ++r) {
                    s[r][jj] = fmaf(q4[r].x, k4.x, s[r][jj]);
                    s[r][jj] = fmaf(q4[r].y, k4.y, s[r][jj]);
                    s[r][jj] = fmaf(q4[r].z, k4.z, s[r][jj]);
                    s[r][jj] = fmaf(q4[r].w, k4.w, s[r][jj]);
                }
            }
        }

        // ---- online softmax (row groups = 16 lanes sharing gq) ----
        float p[4][4];
        #pragma unroll
        for (int r = 0; r < 4; ++r) {
            float mx = fmaxf(fmaxf(s[r][0], s[r][1]), fmaxf(s[r][2], s[r][3]));
            #pragma unroll
            for (int o = 1; o < 16; o <<= 1)
                mx = fmaxf(mx, __shfl_xor_sync(0xffffffffu, mx, o));
            float mnew = fmaxf(m_run[r], mx);
            float alpha = __expf(m_run[r] - mnew);
            m_run[r] = mnew;
            float ls = 0.0f;
            #pragma unroll
            for (int jj = 0; jj < 4; ++jj) {
                p[r][jj] = __expf(s[r][jj] - mnew);
                ls += p[r][jj];
            }
            #pragma unroll
            for (int o = 1; o < 16; o <<= 1)
                ls += __shfl_xor_sync(0xffffffffu, ls, o);
            l_run[r] = l_run[r] * alpha + ls;   // denominator uses UNmasked probs
            #pragma unroll
            for (int c = 0; c < 8; ++c) acc[r][c] *= alpha;
        }

        // ---- dropout mask (JAX partitionable threefry) + store masked P^T ----
        #pragma unroll
        for (int jj = 0; jj < 4; ++jj) {
            uint32_t v = (uint32_t)(vb + g + 16 * jj);
            #pragma unroll
            for (int r = 0; r < 4; ++r) {
                uint32_t m = mbase + ((uint32_t)r << 12) + v;   // flat element index
                uint2 o2 = tf2x32_key0_42(0u, m);               // ctr = (hi=0, lo=m)
                uint32_t bits = o2.x ^ o2.y;                    // 32-bit combine = XOR
                Ps[(g + 16 * jj) * PSTR + qi + r] =
                    (bits < KEEP_THRESH) ? p[r][jj] : 0.0f;
            }
        }
        __syncthreads();  // (c) done reading K / writing Ps

        // ---- load V block into the same buffer (stride H) ----
        #pragma unroll
        for (int i = 0; i < 8; ++i) {
            int idx = tid + i * THREADS;
            int row = idx >> 5, c4 = (idx & 31) << 2;
            *(float4*)(KV + row * H + c4) =
                *(const float4*)(Vg + (size_t)(vb + row) * H + c4);
        }
        __syncthreads();  // (d)

        // ---- O += P V : 4 rows x 8 cols (cols 4g..4g+3 and 64+4g..64+4g+3) ----
        #pragma unroll 2
        for (int j = 0; j < BK; ++j) {
            float4 p4  = *(float4*)(Ps + j * PSTR + qi);
            float4 va  = *(float4*)(KV + j * H + 4 * g);
            float4 vb4 = *(float4*)(KV + j * H + 64 + 4 * g);
            float pr[4] = {p4.x, p4.y, p4.z, p4.w};
            #pragma unroll
            for (int r = 0; r < 4; ++r) {
                acc[r][0] = fmaf(pr[r], va.x,  acc[r][0]);
                acc[r][1] = fmaf(pr[r], va.y,  acc[r][1]);
                acc[r][2] = fmaf(pr[r], va.z,  acc[r][2]);
                acc[r][3] = fmaf(pr[r], va.w,  acc[r][3]);
                acc[r][4] = fmaf(pr[r], vb4.x, acc[r][4]);
                acc[r][5] = fmaf(pr[r], vb4.y, acc[r][5]);
                acc[r][6] = fmaf(pr[r], vb4.z, acc[r][6]);
                acc[r][7] = fmaf(pr[r], vb4.w, acc[r][7]);
            }
        }
    }

    // ---- epilogue: O = acc / (0.9 * l) ----
    #pragma unroll
    for (int r = 0; r < 4; ++r) {
        float inv = 1.0f / (0.9f * l_run[r]);
        size_t base = ((size_t)b * SEQ + qblk + qi + r) * H;
        float4 o0, o1;
        o0.x = acc[r][0] * inv; o0.y = acc[r][1] * inv;
        o0.z = acc[r][2] * inv; o0.w = acc[r][3] * inv;
        o1.x = acc[r][4] * inv; o1.y = acc[r][5] * inv;
        o1.z = acc[r][6] * inv; o1.w = acc[r][7] * inv;
        *(float4*)(Og + base + 4 * g)      = o0;
        *(float4*)(Og + base + 64 + 4 * g) = o1;
    }
}

extern "C" void kernel_launch(void* const* d_in, const int* in_sizes, int n_in,
                              void* d_out, int out_size) {
    const float* Q = (const float*)d_in[0];
    const float* K = (const float*)d_in[1];
    const float* V = (const float*)d_in[2];
    float* O = (float*)d_out;

    (void)in_sizes; (void)n_in; (void)out_size;

    cudaFuncSetAttribute(attn_dropout_kernel,
                         cudaFuncAttributeMaxDynamicSharedMemorySize,
                         SMEM_FLOATS * (int)sizeof(float));
    dim3 grid(SEQ / BQ, 4);
    attn_dropout_kernel<<<grid, THREADS, SMEM_FLOATS * sizeof(float)>>>(Q, K, V, O);
}

// round 4
// speedup vs baseline: 3.6924x; 3.6924x over previous
#include <cuda_runtime.h>
#include <cuda_bf16.h>
#include <cstdint>

// ============================================================================
// Fused flash attention via mma.sync (HMMA, base sm_103 target — tcgen05 is
// not available at the harness's PTX target):
//   O = dropout(softmax(Q K^T * sqrt(128))) V,  B=4, SEQ=4096, H=128, fp32.
// QK and PV run as bf16 m16n8k16 MMAs with 3-way fp32-emulation splits.
// Dropout = JAX partitionable threefry2x32, key (0,42), bits = o1^o2,
// keep <=> bits < 7549747*512  (verified bit-exact in round 2).
// ============================================================================

namespace cfg {
constexpr int H = 128, SEQ = 4096, BQ = 128, BK = 64;
constexpr int NIT = SEQ / BK;                      // 64
constexpr uint32_t KEEP = 3865470464u;
constexpr float SCALE = 11.313708498984760390f;    // sqrt(128)
// padded bf16 smem tiles: row stride 136 elements = 272 bytes
constexpr int RS     = 272;                        // row stride bytes
constexpr int QTILE  = BQ * RS;                    // 34816
constexpr int KTILE  = BK * RS;                    // 17408
constexpr int SM_QHI = 0;
constexpr int SM_QLO = SM_QHI + QTILE;
constexpr int SM_KHI = SM_QLO + QTILE;             // 69632
constexpr int SM_KLO = SM_KHI + KTILE;
constexpr int SM_VHI = SM_KLO + KTILE;
constexpr int SM_VLO = SM_VHI + KTILE;
constexpr int SMEM_TOTAL = SM_VLO + KTILE;         // 139264 B
}

// ---------------------------------------------------------------------------
// threefry-2x32-20, key (0,42), ctr (0,m) -> o1 ^ o2  (exact JAX partitionable)
#define TF_ROUND(a, b, r) { (a) += (b); (b) = __funnelshift_l((b), (b), (r)); (b) ^= (a); }
__device__ __forceinline__ uint32_t tf_bits(uint32_t b) {
    const uint32_t K1 = 42u, K2 = 0x1BD11BF0u;
    uint32_t a = 0u;
    b += K1;
    TF_ROUND(a,b,13) TF_ROUND(a,b,15) TF_ROUND(a,b,26) TF_ROUND(a,b,6)
    a += K1; b += K2 + 1u;
    TF_ROUND(a,b,17) TF_ROUND(a,b,29) TF_ROUND(a,b,16) TF_ROUND(a,b,24)
    a += K2; b += 2u;
    TF_ROUND(a,b,13) TF_ROUND(a,b,15) TF_ROUND(a,b,26) TF_ROUND(a,b,6)
    b += K1 + 3u;
    TF_ROUND(a,b,17) TF_ROUND(a,b,29) TF_ROUND(a,b,16) TF_ROUND(a,b,24)
    a += K1; b += K2 + 4u;
    TF_ROUND(a,b,13) TF_ROUND(a,b,15) TF_ROUND(a,b,26) TF_ROUND(a,b,6)
    a += K2; b += 5u;
    return a ^ b;
}

// ---------------------------------------------------------------------------
__device__ __forceinline__ uint32_t smem_u32(const void* p) {
    uint32_t a;
    asm("{ .reg .u64 t; cvta.to.shared.u64 t, %1; cvt.u32.u64 %0, t; }" : "=r"(a) : "l"(p));
    return a;
}
__device__ __forceinline__ void ldsm4(uint32_t* r, uint32_t addr) {
    asm volatile("ldmatrix.sync.aligned.m8n8.x4.shared.b16 {%0,%1,%2,%3}, [%4];"
                 : "=r"(r[0]), "=r"(r[1]), "=r"(r[2]), "=r"(r[3]) : "r"(addr));
}
__device__ __forceinline__ void ldsm4t(uint32_t* r, uint32_t addr) {
    asm volatile("ldmatrix.sync.aligned.m8n8.x4.trans.shared.b16 {%0,%1,%2,%3}, [%4];"
                 : "=r"(r[0]), "=r"(r[1]), "=r"(r[2]), "=r"(r[3]) : "r"(addr));
}
__device__ __forceinline__ void mma16816(float* d, const uint32_t* a, uint32_t b0, uint32_t b1) {
    asm volatile("mma.sync.aligned.m16n8k16.row.col.f32.bf16.bf16.f32 "
                 "{%0,%1,%2,%3}, {%4,%5,%6,%7}, {%8,%9}, {%0,%1,%2,%3};"
                 : "+f"(d[0]), "+f"(d[1]), "+f"(d[2]), "+f"(d[3])
                 : "r"(a[0]), "r"(a[1]), "r"(a[2]), "r"(a[3]), "r"(b0), "r"(b1));
}
__device__ __forceinline__ uint32_t pack2(__nv_bfloat16 x, __nv_bfloat16 y) {
    __nv_bfloat162 t; t.x = x; t.y = y;
    return *reinterpret_cast<uint32_t*>(&t);
}
// split a float pair into hi/lo bf16x2 packs
__device__ __forceinline__ void split2(float x, float y, uint32_t& hi, uint32_t& lo) {
    __nv_bfloat16 hx = __float2bfloat16(x), hy = __float2bfloat16(y);
    hi = pack2(hx, hy);
    lo = pack2(__float2bfloat16(x - __bfloat162float(hx)),
               __float2bfloat16(y - __bfloat162float(hy)));
}

// ---------------------------------------------------------------------------
__global__ __launch_bounds__(256, 1)
void attn_hmma_kernel(const float* __restrict__ Qg_,
                      const float* __restrict__ Kg_,
                      const float* __restrict__ Vg_,
                      float* __restrict__ Og) {
    using namespace cfg;
    extern __shared__ char smem[];
    const uint32_t sb = smem_u32(smem);

    const int tid  = threadIdx.x;
    const int wid  = tid >> 5;
    const int lane = tid & 31;
    const int qblk = blockIdx.x * BQ;
    const int bb   = blockIdx.y;

    const float* Qg = Qg_ + (size_t)bb * SEQ * H;
    const float* Kg = Kg_ + (size_t)bb * SEQ * H;
    const float* Vg = Vg_ + (size_t)bb * SEQ * H;

    // ---- load Q tile once (scaled), split to Qhi/Qlo smem ----
    #pragma unroll
    for (int i = 0; i < 16; ++i) {                 // 128 rows x 32 float4
        int idx = tid + i * 256;
        int row = idx >> 5, c4 = (idx & 31) << 2;
        float4 v = *(const float4*)(Qg + (size_t)(qblk + row) * H + c4);
        v.x *= SCALE; v.y *= SCALE; v.z *= SCALE; v.w *= SCALE;
        uint32_t h0, l0, h1, l1;
        split2(v.x, v.y, h0, l0); split2(v.z, v.w, h1, l1);
        uint2 hp = make_uint2(h0, h1), lp = make_uint2(l0, l1);
        *(uint2*)(smem + SM_QHI + row * RS + c4 * 2) = hp;
        *(uint2*)(smem + SM_QLO + row * RS + c4 * 2) = lp;
    }

    // per-lane ldmatrix base addresses
    const uint32_t abase = sb + SM_QHI + (wid * 16 + (lane & 15)) * RS + (lane >> 4) * 16;
    const uint32_t bbase = sb + SM_KHI + (lane & 15) * RS + (lane >> 4) * 16;
    const uint32_t vbase = sb + SM_VHI + (lane & 15) * RS + (lane >> 4) * 16;

    // accumulators: O 16 tiles (h), fragments row0=lane/4, row1=+8
    float o[16][4];
    #pragma unroll
    for (int j = 0; j < 16; ++j)
        #pragma unroll
        for (int c = 0; c < 4; ++c) o[j][c] = 0.0f;
    float m0 = -1e30f, m1 = -1e30f, l0 = 0.0f, l1 = 0.0f;

    const int row_g0 = qblk + wid * 16 + (lane >> 2);   // global q row (lo)
    const uint32_t mrow0 = ((uint32_t)bb << 24) | ((uint32_t)row_g0 << 12);
    const uint32_t mrow1 = mrow0 + (8u << 12);

    for (int it = 0; it < NIT; ++it) {
        const int vb = it * BK;
        __syncthreads();   // previous iter's smem reads done

        // ---- load K and V tiles (64x128 each), split ----
        #pragma unroll
        for (int i = 0; i < 8; ++i) {
            int idx = tid + i * 256;
            int row = idx >> 5, c4 = (idx & 31) << 2;
            float4 v = *(const float4*)(Kg + (size_t)(vb + row) * H + c4);
            uint32_t h0, lo0, h1, lo1;
            split2(v.x, v.y, h0, lo0); split2(v.z, v.w, h1, lo1);
            *(uint2*)(smem + SM_KHI + row * RS + c4 * 2) = make_uint2(h0, h1);
            *(uint2*)(smem + SM_KLO + row * RS + c4 * 2) = make_uint2(lo0, lo1);
        }
        #pragma unroll
        for (int i = 0; i < 8; ++i) {
            int idx = tid + i * 256;
            int row = idx >> 5, c4 = (idx & 31) << 2;
            float4 v = *(const float4*)(Vg + (size_t)(vb + row) * H + c4);
            uint32_t h0, lo0, h1, lo1;
            split2(v.x, v.y, h0, lo0); split2(v.z, v.w, h1, lo1);
            *(uint2*)(smem + SM_VHI + row * RS + c4 * 2) = make_uint2(h0, h1);
            *(uint2*)(smem + SM_VLO + row * RS + c4 * 2) = make_uint2(lo0, lo1);
        }
        __syncthreads();

        // ---- S = Qh*Kh + Qh*Kl + Ql*Kh  (16 x 64 per warp, 8 n-tiles) ----
        float s[8][4];
        #pragma unroll
        for (int j = 0; j < 8; ++j)
            #pragma unroll
            for (int c = 0; c < 4; ++c) s[j][c] = 0.0f;

        #pragma unroll
        for (int ks = 0; ks < 8; ++ks) {
            uint32_t ah[4], al[4];
            ldsm4(ah, abase + ks * 32);
            ldsm4(al, abase + QTILE + ks * 32);
            #pragma unroll
            for (int ng = 0; ng < 4; ++ng) {
                uint32_t bh[4], bl[4];
                ldsm4(bh, bbase + ng * (16 * RS) + ks * 32);
                ldsm4(bl, bbase + KTILE + ng * (16 * RS) + ks * 32);
                mma16816(s[2*ng],   ah, bh[0], bh[2]);
                mma16816(s[2*ng+1], ah, bh[1], bh[3]);
                mma16816(s[2*ng],   ah, bl[0], bl[2]);
                mma16816(s[2*ng+1], ah, bl[1], bl[3]);
                mma16816(s[2*ng],   al, bh[0], bh[2]);
                mma16816(s[2*ng+1], al, bh[1], bh[3]);
            }
        }

        // ---- online softmax (rows split across quad lanes) ----
        float mx0 = -1e30f, mx1 = -1e30f;
        #pragma unroll
        for (int j = 0; j < 8; ++j) {
            mx0 = fmaxf(mx0, fmaxf(s[j][0], s[j][1]));
            mx1 = fmaxf(mx1, fmaxf(s[j][2], s[j][3]));
        }
        #pragma unroll
        for (int off = 1; off < 4; off <<= 1) {
            mx0 = fmaxf(mx0, __shfl_xor_sync(0xffffffffu, mx0, off));
            mx1 = fmaxf(mx1, __shfl_xor_sync(0xffffffffu, mx1, off));
        }
        float mn0 = fmaxf(m0, mx0), mn1 = fmaxf(m1, mx1);
        float al0 = __expf(m0 - mn0), al1 = __expf(m1 - mn1);
        m0 = mn0; m1 = mn1;

        float ls0 = 0.0f, ls1 = 0.0f;
        #pragma unroll
        for (int j = 0; j < 8; ++j) {
            s[j][0] = __expf(s[j][0] - mn0); ls0 += s[j][0];
            s[j][1] = __expf(s[j][1] - mn0); ls0 += s[j][1];
            s[j][2] = __expf(s[j][2] - mn1); ls1 += s[j][2];
            s[j][3] = __expf(s[j][3] - mn1); ls1 += s[j][3];
        }
        #pragma unroll
        for (int off = 1; off < 4; off <<= 1) {
            ls0 += __shfl_xor_sync(0xffffffffu, ls0, off);
            ls1 += __shfl_xor_sync(0xffffffffu, ls1, off);
        }
        l0 = l0 * al0 + ls0;
        l1 = l1 * al1 + ls1;

        // rescale O
        #pragma unroll
        for (int j = 0; j < 16; ++j) {
            o[j][0] *= al0; o[j][1] *= al0;
            o[j][2] *= al1; o[j][3] *= al1;
        }

        // ---- dropout (exact threefry) + build P hi/lo A-fragments ----
        uint32_t phi[4][4], plo[4][4];
        #pragma unroll
        for (int ks = 0; ks < 4; ++ks) {
            #pragma unroll
            for (int h2 = 0; h2 < 2; ++h2) {
                int j = 2 * ks + h2;
                uint32_t c = (uint32_t)(vb + j * 8 + (lane & 3) * 2);
                float p0 = (tf_bits(mrow0 + c)      < KEEP) ? s[j][0] : 0.0f;
                float p1 = (tf_bits(mrow0 + c + 1u) < KEEP) ? s[j][1] : 0.0f;
                float p2 = (tf_bits(mrow1 + c)      < KEEP) ? s[j][2] : 0.0f;
                float p3 = (tf_bits(mrow1 + c + 1u) < KEEP) ? s[j][3] : 0.0f;
                split2(p0, p1, phi[ks][h2 * 2],     plo[ks][h2 * 2]);
                split2(p2, p3, phi[ks][h2 * 2 + 1], plo[ks][h2 * 2 + 1]);
            }
        }

        // ---- O += Ph*Vh + Ph*Vl + Pl*Vh ----
        #pragma unroll
        for (int ks = 0; ks < 4; ++ks) {
            #pragma unroll
            for (int hg = 0; hg < 8; ++hg) {
                uint32_t bh[4], bl[4];
                ldsm4t(bh, vbase + ks * (16 * RS) + hg * 32);
                ldsm4t(bl, vbase + KTILE + ks * (16 * RS) + hg * 32);
                mma16816(o[2*hg],   phi[ks], bh[0], bh[1]);
                mma16816(o[2*hg+1], phi[ks], bh[2], bh[3]);
                mma16816(o[2*hg],   phi[ks], bl[0], bl[1]);
                mma16816(o[2*hg+1], phi[ks], bl[2], bl[3]);
                mma16816(o[2*hg],   plo[ks], bh[0], bh[1]);
                mma16816(o[2*hg+1], plo[ks], bh[2], bh[3]);
            }
        }
    }

    // ---- epilogue: O /= (0.9 * l) ----
    float inv0 = 1.0f / (0.9f * l0);
    float inv1 = 1.0f / (0.9f * l1);
    float* out0 = Og + ((size_t)bb * SEQ + row_g0) * H;
    float* out1 = out0 + 8 * H;
    #pragma unroll
    for (int j = 0; j < 16; ++j) {
        int h = j * 8 + (lane & 3) * 2;
        float2 v0 = make_float2(o[j][0] * inv0, o[j][1] * inv0);
        float2 v1 = make_float2(o[j][2] * inv1, o[j][3] * inv1);
        *(float2*)(out0 + h) = v0;
        *(float2*)(out1 + h) = v1;
    }
}

extern "C" void kernel_launch(void* const* d_in, const int* in_sizes, int n_in,
                              void* d_out, int out_size) {
    const float* Q = (const float*)d_in[0];
    const float* K = (const float*)d_in[1];
    const float* V = (const float*)d_in[2];
    float* O = (float*)d_out;
    (void)in_sizes; (void)n_in; (void)out_size;

    cudaFuncSetAttribute(attn_hmma_kernel,
                         cudaFuncAttributeMaxDynamicSharedMemorySize, cfg::SMEM_TOTAL);
    dim3 grid(cfg::SEQ / cfg::BQ, 4);
    attn_hmma_kernel<<<grid, 256, cfg::SMEM_TOTAL>>>(Q, K, V, O);
}